// round 3
// baseline (speedup 1.0000x reference)
#include <cuda_runtime.h>

#define D_IN   1024
#define D_FEAT 4096
#define DEG    4
#define RPB    8          // rows per block

// Table layout (per degree d, region of 8192 floats):
//   phys = d*8192 + idx*8 + (r ^ ((idx>>2)&7))
// - gather LDS.32 (fixed idx, lanes sweep r=0..7): idx's 8 rows fill a whole
//   aligned 8-bank group keyed by idx&3 -> conflicts only between the 4
//   features of one instruction colliding mod 4 (E[max] = 2.125).
// - table STS (warp owns row r, lanes sweep i=k*32+lane): conflict-free.
// Phase-1 scratch (32x32 transpose) reuses the table region: warp (d,r) uses
// floats [d*8192 + r*1024, +1024) before the table is written (barrier between).

__global__ __launch_bounds__(1024, 1)
void srht_kernel(const float* __restrict__ x,
                 const float* __restrict__ rad,
                 const int*   __restrict__ perm,
                 const float* __restrict__ log_ls,
                 const float* __restrict__ log_var,
                 float* __restrict__ out)
{
    extern __shared__ float sw[];   // DEG * 8192 floats = 128 KB

    const int tid  = threadIdx.x;
    const int wid  = tid >> 5;
    const int lane = tid & 31;
    const int row0 = blockIdx.x * RPB;

    const float inv_ls = expf(-log_ls[0]);

    // ---------------- Phase 1: FWHT (shuffle-free, via smem transpose) ----------------
    {
        const int d = wid >> 3;     // 0..3
        const int r = wid & 7;      // 0..7
        // lane holds j = lane*32 + k  (low 5 bits of j live in register index k)
        const float4* __restrict__ xr4 =
            (const float4*)(x + (size_t)(row0 + r) * D_IN + lane * 32);
        const float4* __restrict__ rd4 =
            (const float4*)(rad + d * D_IN + lane * 32);

        float v[32];
        #pragma unroll
        for (int c = 0; c < 8; c++) {
            float4 xv = xr4[c];
            float4 rv = rd4[c];
            v[4*c+0] = xv.x * rv.x * inv_ls;
            v[4*c+1] = xv.y * rv.y * inv_ls;
            v[4*c+2] = xv.z * rv.z * inv_ls;
            v[4*c+3] = xv.w * rv.w * inv_ls;
        }

        // stages h = 1,2,4,8,16 (low bits, in registers)
        #pragma unroll
        for (int mb = 0; mb < 5; mb++) {
            const int m = 1 << mb;
            #pragma unroll
            for (int k = 0; k < 32; k++) {
                if ((k & m) == 0) {
                    float a = v[k], b = v[k + m];
                    v[k] = a + b;  v[k + m] = a - b;
                }
            }
        }

        // 32x32 transpose through warp-private scratch (inside table region d)
        float* __restrict__ scr = sw + wid * 1024;   // == d*8192 + r*1024
        #pragma unroll
        for (int c = 0; c < 8; c++) {   // STS.128, conflict-free (16B-group xor swizzle)
            *(float4*)(scr + lane * 32 + ((c ^ (lane & 7)) << 2)) =
                make_float4(v[4*c+0], v[4*c+1], v[4*c+2], v[4*c+3]);
        }
        __syncwarp();
        const int l2 = lane >> 2;
        const int l3 = lane & 3;
        #pragma unroll
        for (int k = 0; k < 32; k++) {  // transposed scalar LDS, conflict-free
            v[k] = scr[k * 32 + ((l2 ^ (k & 7)) << 2) + l3];
        }

        // stages h = 32..512 (high bits, now in registers)
        #pragma unroll
        for (int mb = 0; mb < 5; mb++) {
            const int m = 1 << mb;
            #pragma unroll
            for (int k = 0; k < 32; k++) {
                if ((k & m) == 0) {
                    float a = v[k], b = v[k + m];
                    v[k] = a + b;  v[k + m] = a - b;
                }
            }
        }

        // all warps must finish reading scratch before table writes clobber it
        __syncthreads();

        float* __restrict__ swd = sw + d * (D_IN * RPB);
        #pragma unroll
        for (int k = 0; k < 32; k++) {  // conflict-free scalar STS
            int i = k * 32 + lane;
            swd[i * 8 + (r ^ ((i >> 2) & 7))] = v[k];
        }
    }
    __syncthreads();

    // ---------- Phase 2: permutation gather + product across degrees ----------
    // Lane layout: r = lane>>2 (row 0..7), c = lane&3 (feature quad).
    // Each thread owns 4 consecutive features -> STG.128.
    const float oscale = expf(0.5f * log_var[0]) * (1.0f / 64.0f);  // / sqrt(4096)
    const int gr = lane >> 2;
    const int gc = lane & 3;
    float* __restrict__ outr = out + (size_t)(row0 + gr) * D_FEAT;

    #pragma unroll
    for (int it = 0; it < 8; it++) {
        const int fb = it * 512 + wid * 16 + gc * 4;   // base feature of this thread's quad

        // hoisted vector perm loads (one LDG.128 per degree, 8-lane broadcast)
        int4 p[DEG];
        #pragma unroll
        for (int d = 0; d < DEG; d++)
            p[d] = *(const int4*)(perm + d * D_FEAT + fb);

        float acc0 = oscale, acc1 = oscale, acc2 = oscale, acc3 = oscale;
        #pragma unroll
        for (int d = 0; d < DEG; d++) {
            const float* __restrict__ swd = sw + d * (D_IN * RPB);
            const int i0 = p[d].x, i1 = p[d].y, i2 = p[d].z, i3 = p[d].w;
            acc0 *= swd[i0 * 8 + (gr ^ ((i0 >> 2) & 7))];
            acc1 *= swd[i1 * 8 + (gr ^ ((i1 >> 2) & 7))];
            acc2 *= swd[i2 * 8 + (gr ^ ((i2 >> 2) & 7))];
            acc3 *= swd[i3 * 8 + (gr ^ ((i3 >> 2) & 7))];
        }
        *reinterpret_cast<float4*>(outr + fb) = make_float4(acc0, acc1, acc2, acc3);
    }
}

extern "C" void kernel_launch(void* const* d_in, const int* in_sizes, int n_in,
                              void* d_out, int out_size)
{
    const float* x   = (const float*)d_in[0];
    const float* rad = (const float*)d_in[1];
    const int*   pm  = (const int*)d_in[2];
    const float* lls = (const float*)d_in[3];
    const float* lv  = (const float*)d_in[4];
    float* out = (float*)d_out;

    const int rows = in_sizes[0] / D_IN;                     // 16384
    const int smem = DEG * D_IN * RPB * (int)sizeof(float);  // 131072 B

    cudaFuncSetAttribute(srht_kernel,
                         cudaFuncAttributeMaxDynamicSharedMemorySize, smem);
    srht_kernel<<<rows / RPB, 1024, smem>>>(x, rad, pm, lls, lv, out);
}

// round 4
// speedup vs baseline: 1.8712x; 1.8712x over previous
#include <cuda_runtime.h>
#include <cuda_fp16.h>

#define D_IN   1024
#define D_FEAT 4096
#define DEG    4
#define RPB    8

// fp16 table, per degree d: 1024 idx x 16B. Within an idx's 16B, the 4
// 32-bit words hold row-pairs, permuted: word w holds rows {2p, 2p+1} with
// p = w ^ s(idx), s(idx) = (idx>>3)&3; even row in the low half.
//  - phase-1 STS.U16 (warp owns row r, lanes sweep i=k*32+lane):
//    bank = 4*(lane&7) + ((r>>1) ^ ((lane>>3)&3))  -> 32 distinct: conflict-free.
//  - phase-2 gather: one LDS.128 per lane fetches a whole idx (8 rows);
//    bank-quad = idx&7, E[max of 32 idx over 8 quads] ~ 6.7 cyc/instr
//    for 512B delivered (vs 2.125cyc/128B with the fp32 scalar scheme).

__global__ __launch_bounds__(512, 2)
void srht_kernel(const float* __restrict__ x,
                 const float* __restrict__ rad,
                 const int*   __restrict__ perm,
                 const float* __restrict__ log_ls,
                 const float* __restrict__ log_var,
                 float* __restrict__ out)
{
    extern __shared__ __align__(16) unsigned char smem_raw[];
    __half*      tab  = reinterpret_cast<__half*>(smem_raw);       // [DEG][1024][8] swizzled
    const uint4* tab4 = reinterpret_cast<const uint4*>(smem_raw);  // [DEG][1024]

    const int tid  = threadIdx.x;
    const int wid  = tid >> 5;          // 0..15
    const int lane = tid & 31;
    const int row0 = blockIdx.x * RPB;

    const float inv_ls = expf(-log_ls[0]);

    // ---------------- Phase 1: FWHT (R1 shuffle scheme), fp16 table store ----------------
    {
        const int d = wid >> 2;                 // 0..3
        #pragma unroll
        for (int rr = 0; rr < 2; rr++) {
            const int r = (wid & 3) * 2 + rr;   // 0..7
            const float* __restrict__ xr = x + (size_t)(row0 + r) * D_IN;
            const float* __restrict__ rd = rad + d * D_IN;

            float v[32];                        // lane holds i = k*32 + lane
            #pragma unroll
            for (int k = 0; k < 32; k++) {
                int i = k * 32 + lane;
                v[k] = xr[i] * rd[i] * inv_ls;
            }

            // lane-bit stages h = 1..16 via shuffle (separate pipe, empirically cheap)
            #pragma unroll
            for (int hb = 0; hb < 5; hb++) {
                const int h = 1 << hb;
                const bool up = (lane & h) != 0;
                #pragma unroll
                for (int k = 0; k < 32; k++) {
                    float o = __shfl_xor_sync(0xffffffffu, v[k], h);
                    v[k] = up ? (o - v[k]) : (v[k] + o);
                }
            }
            // register-bit stages h = 32..512
            #pragma unroll
            for (int mb = 0; mb < 5; mb++) {
                const int m = 1 << mb;
                #pragma unroll
                for (int k = 0; k < 32; k++) {
                    if ((k & m) == 0) {
                        float a = v[k], b = v[k + m];
                        v[k] = a + b;  v[k + m] = a - b;
                    }
                }
            }

            // conflict-free 16-bit swizzled stores
            const int ph = r >> 1, rh = r & 1;
            #pragma unroll
            for (int k = 0; k < 32; k++) {
                const int i = k * 32 + lane;
                const int w = ph ^ ((i >> 3) & 3);
                tab[d * 8192 + i * 8 + w * 2 + rh] = __float2half_rn(v[k]);
            }
        }
    }
    __syncthreads();

    // ---------------- Phase 2: gather (LDS.128/lane) + product + coalesced stores ----------------
    const float oscale = expf(0.5f * log_var[0]) * (1.0f / 64.0f);   // / sqrt(4096)
    float* __restrict__ ob = out + (size_t)row0 * D_FEAT;

    #pragma unroll
    for (int it = 0; it < 8; it++) {
        const int f = it * 512 + wid * 32 + lane;   // this lane's feature

        int idx[DEG];
        #pragma unroll
        for (int dd = 0; dd < DEG; dd++)            // coalesced LDG.32 x4, hoisted for MLP
            idx[dd] = perm[dd * D_FEAT + f];

        float a0 = oscale, a1 = oscale, a2 = oscale, a3 = oscale;
        float a4 = oscale, a5 = oscale, a6 = oscale, a7 = oscale;

        #pragma unroll
        for (int dd = 0; dd < DEG; dd++) {
            uint4 h = tab4[dd * 1024 + idx[dd]];    // whole idx: 8 rows fp16
            const int s = (idx[dd] >> 3) & 3;
            // branch-free un-swizzle: h'[w] = h[w ^ s]
            unsigned hx = (s & 1) ? h.y : h.x;
            unsigned hy = (s & 1) ? h.x : h.y;
            unsigned hz = (s & 1) ? h.w : h.z;
            unsigned hw = (s & 1) ? h.z : h.w;
            unsigned g0 = (s & 2) ? hz : hx;
            unsigned g1 = (s & 2) ? hw : hy;
            unsigned g2 = (s & 2) ? hx : hz;
            unsigned g3 = (s & 2) ? hy : hw;

            float2 f0 = __half22float2(*reinterpret_cast<__half2*>(&g0));
            float2 f1 = __half22float2(*reinterpret_cast<__half2*>(&g1));
            float2 f2 = __half22float2(*reinterpret_cast<__half2*>(&g2));
            float2 f3 = __half22float2(*reinterpret_cast<__half2*>(&g3));
            a0 *= f0.x;  a1 *= f0.y;
            a2 *= f1.x;  a3 *= f1.y;
            a4 *= f2.x;  a5 *= f2.y;
            a6 *= f3.x;  a7 *= f3.y;
        }

        // 8 fully-coalesced 128B row stores
        ob[0 * D_FEAT + f] = a0;
        ob[1 * D_FEAT + f] = a1;
        ob[2 * D_FEAT + f] = a2;
        ob[3 * D_FEAT + f] = a3;
        ob[4 * D_FEAT + f] = a4;
        ob[5 * D_FEAT + f] = a5;
        ob[6 * D_FEAT + f] = a6;
        ob[7 * D_FEAT + f] = a7;
    }
}

extern "C" void kernel_launch(void* const* d_in, const int* in_sizes, int n_in,
                              void* d_out, int out_size)
{
    const float* x   = (const float*)d_in[0];
    const float* rad = (const float*)d_in[1];
    const int*   pm  = (const int*)d_in[2];
    const float* lls = (const float*)d_in[3];
    const float* lv  = (const float*)d_in[4];
    float* out = (float*)d_out;

    const int rows = in_sizes[0] / D_IN;                       // 16384
    const int smem = DEG * D_IN * RPB * (int)sizeof(__half);   // 65536 B

    cudaFuncSetAttribute(srht_kernel,
                         cudaFuncAttributeMaxDynamicSharedMemorySize, smem);
    srht_kernel<<<rows / RPB, 512, smem>>>(x, rad, pm, lls, lv, out);
}

// round 5
// speedup vs baseline: 1.9493x; 1.0417x over previous
#include <cuda_runtime.h>
#include <cuda_fp16.h>

#define D_IN   1024
#define D_FEAT 4096
#define DEG    4
#define RPB    8

// fp16 table, per degree d: 1024 idx x 16B; word w of idx holds row-pair
// p = w ^ s(idx), s = (idx>>3)&3, even row in low half. Phase-1 STS.U16 is
// conflict-free; phase-2 gather is one LDS.128 per (feature, degree).
// rad (+-1) is compressed to sign words: radw[d][k] bit j = sign(rad[d][k*32+j]).
// perm is repacked per launch into ushort4 (one LDG.64 per feature covers all 4 degrees).

__device__ ushort4 g_perm16[D_FEAT];

__global__ void pack_perm_kernel(const int* __restrict__ perm) {
    int f = blockIdx.x * 256 + threadIdx.x;
    if (f < D_FEAT) {
        g_perm16[f] = make_ushort4((unsigned short)perm[f],
                                   (unsigned short)perm[D_FEAT + f],
                                   (unsigned short)perm[2 * D_FEAT + f],
                                   (unsigned short)perm[3 * D_FEAT + f]);
    }
}

__global__ __launch_bounds__(512, 2)
void srht_kernel(const float* __restrict__ x,
                 const float* __restrict__ rad,
                 const float* __restrict__ log_ls,
                 const float* __restrict__ log_var,
                 float* __restrict__ out)
{
    extern __shared__ __align__(16) unsigned char smem_raw[];
    __half*       tab   = reinterpret_cast<__half*>(smem_raw);         // [DEG][1024][8]
    const uint4*  tab4  = reinterpret_cast<const uint4*>(smem_raw);    // [DEG][1024]
    unsigned*     radw  = reinterpret_cast<unsigned*>(smem_raw + DEG * D_IN * RPB * 2);
    const uint4*  radw4 = reinterpret_cast<const uint4*>(radw);        // [DEG][8]

    const int tid  = threadIdx.x;
    const int wid  = tid >> 5;          // 0..15
    const int lane = tid & 31;
    const int row0 = blockIdx.x * RPB;

    // ---------------- Phase 0: build rad sign words (warps 0..3) ----------------
    if (wid < 4) {
        const float* __restrict__ rd = rad + wid * D_IN;
        #pragma unroll
        for (int k = 0; k < 32; k++) {
            float f = rd[k * 32 + lane];
            unsigned m = __ballot_sync(0xffffffffu, f < 0.0f);
            if (lane == (k & 31)) radw[wid * 32 + k] = m;
        }
    }
    __syncthreads();

    // ---------------- Phase 1: FWHT (shuffle scheme), sign via XOR ----------------
    {
        const int d = wid >> 2;                 // 0..3
        const int sh = 31 - lane;               // puts bit 'lane' at bit 31
        #pragma unroll
        for (int rr = 0; rr < 2; rr++) {
            const int r = (wid & 3) * 2 + rr;   // 0..7
            const float* __restrict__ xr = x + (size_t)(row0 + r) * D_IN;

            float v[32];                        // lane holds i = k*32 + lane
            #pragma unroll
            for (int kc = 0; kc < 8; kc++) {
                uint4 wq = radw4[d * 8 + kc];   // broadcast LDS.128: signs for k = 4kc..4kc+3
                #pragma unroll
                for (int j = 0; j < 4; j++) {
                    const int k = kc * 4 + j;
                    unsigned w = (j == 0) ? wq.x : (j == 1) ? wq.y : (j == 2) ? wq.z : wq.w;
                    unsigned xb = __float_as_uint(xr[k * 32 + lane]);
                    v[k] = __uint_as_float(xb ^ ((w << sh) & 0x80000000u));
                }
            }

            // lane-bit stages h = 1..16 via shuffle
            #pragma unroll
            for (int hb = 0; hb < 5; hb++) {
                const int h = 1 << hb;
                const bool up = (lane & h) != 0;
                #pragma unroll
                for (int k = 0; k < 32; k++) {
                    float o = __shfl_xor_sync(0xffffffffu, v[k], h);
                    v[k] = up ? (o - v[k]) : (v[k] + o);
                }
            }
            // register-bit stages h = 32..512
            #pragma unroll
            for (int mb = 0; mb < 5; mb++) {
                const int m = 1 << mb;
                #pragma unroll
                for (int k = 0; k < 32; k++) {
                    if ((k & m) == 0) {
                        float a = v[k], b = v[k + m];
                        v[k] = a + b;  v[k + m] = a - b;
                    }
                }
            }

            // conflict-free 16-bit swizzled table stores
            const int ph = r >> 1, rh = r & 1;
            #pragma unroll
            for (int k = 0; k < 32; k++) {
                const int i = k * 32 + lane;
                const int w = ph ^ ((i >> 3) & 3);
                tab[d * 8192 + i * 8 + w * 2 + rh] = __float2half_rn(v[k]);
            }
        }
    }
    __syncthreads();

    // ---------------- Phase 2: gather (LDS.128/lane) + product + coalesced stores ----------------
    // oscale folds exp(log_var/2), 1/sqrt(D_FEAT), and inv_lengthscale^DEG
    const float oscale = expf(0.5f * log_var[0] - 4.0f * log_ls[0]) * (1.0f / 64.0f);
    float* __restrict__ ob = out + (size_t)row0 * D_FEAT;

    #pragma unroll
    for (int it = 0; it < 8; it++) {
        const int f = it * 512 + wid * 32 + lane;   // this lane's feature

        const ushort4 pp = g_perm16[f];             // one LDG.64: all 4 degree-indices
        const int idx0 = pp.x, idx1 = pp.y, idx2 = pp.z, idx3 = pp.w;

        float a0 = oscale, a1 = oscale, a2 = oscale, a3 = oscale;
        float a4 = oscale, a5 = oscale, a6 = oscale, a7 = oscale;

        #pragma unroll
        for (int dd = 0; dd < DEG; dd++) {
            const int idx = (dd == 0) ? idx0 : (dd == 1) ? idx1 : (dd == 2) ? idx2 : idx3;
            uint4 h = tab4[dd * 1024 + idx];        // whole idx: 8 rows fp16
            const int s = (idx >> 3) & 3;
            // branch-free un-swizzle: h'[w] = h[w ^ s]
            unsigned hx = (s & 1) ? h.y : h.x;
            unsigned hy = (s & 1) ? h.x : h.y;
            unsigned hz = (s & 1) ? h.w : h.z;
            unsigned hw = (s & 1) ? h.z : h.w;
            unsigned g0 = (s & 2) ? hz : hx;
            unsigned g1 = (s & 2) ? hw : hy;
            unsigned g2 = (s & 2) ? hx : hz;
            unsigned g3 = (s & 2) ? hy : hw;

            float2 f0 = __half22float2(*reinterpret_cast<__half2*>(&g0));
            float2 f1 = __half22float2(*reinterpret_cast<__half2*>(&g1));
            float2 f2 = __half22float2(*reinterpret_cast<__half2*>(&g2));
            float2 f3 = __half22float2(*reinterpret_cast<__half2*>(&g3));
            a0 *= f0.x;  a1 *= f0.y;
            a2 *= f1.x;  a3 *= f1.y;
            a4 *= f2.x;  a5 *= f2.y;
            a6 *= f3.x;  a7 *= f3.y;
        }

        // 8 fully-coalesced 128B row stores
        ob[0 * D_FEAT + f] = a0;
        ob[1 * D_FEAT + f] = a1;
        ob[2 * D_FEAT + f] = a2;
        ob[3 * D_FEAT + f] = a3;
        ob[4 * D_FEAT + f] = a4;
        ob[5 * D_FEAT + f] = a5;
        ob[6 * D_FEAT + f] = a6;
        ob[7 * D_FEAT + f] = a7;
    }
}

extern "C" void kernel_launch(void* const* d_in, const int* in_sizes, int n_in,
                              void* d_out, int out_size)
{
    const float* x   = (const float*)d_in[0];
    const float* rad = (const float*)d_in[1];
    const int*   pm  = (const int*)d_in[2];
    const float* lls = (const float*)d_in[3];
    const float* lv  = (const float*)d_in[4];
    float* out = (float*)d_out;

    const int rows = in_sizes[0] / D_IN;                            // 16384
    const int smem = DEG * D_IN * RPB * (int)sizeof(__half) + 512;  // 66048 B

    pack_perm_kernel<<<D_FEAT / 256, 256>>>(pm);

    cudaFuncSetAttribute(srht_kernel,
                         cudaFuncAttributeMaxDynamicSharedMemorySize, smem);
    srht_kernel<<<rows / RPB, 512, smem>>>(x, rad, lls, lv, out);
}